// round 4
// baseline (speedup 1.0000x reference)
#include <cuda_runtime.h>
#include <cstdint>

#define HID    1024
#define INPD   512
#define BATCH  128
#define TSTEPS 256
#define G4H    4096
#define KC     32

// ---- device-global scratch (no allocations allowed) ----
__device__ float    g_XS[134217728];        // [t][gate*1024+j][b]  fp32, 512 MB
__device__ float    g_H[2][HID * BATCH];    // h ping-pong
__device__ unsigned g_bar;                  // software grid barrier counter

__device__ __forceinline__ uint32_t f2tf(float f) {
    uint32_t u;
    asm("cvt.rna.tf32.f32 %0, %1;" : "=r"(u) : "f"(f));
    return u;
}

__device__ __forceinline__ void mma8(float* d, const uint32_t* a, const uint32_t* b) {
    asm volatile(
        "mma.sync.aligned.m16n8k8.row.col.f32.tf32.tf32.f32 "
        "{%0,%1,%2,%3}, {%4,%5,%6,%7}, {%8,%9}, {%0,%1,%2,%3};"
        : "+f"(d[0]), "+f"(d[1]), "+f"(d[2]), "+f"(d[3])
        : "r"(a[0]), "r"(a[1]), "r"(a[2]), "r"(a[3]), "r"(b[0]), "r"(b[1]));
}

__device__ __forceinline__ const float* sel4(const float* a, const float* b,
                                             const float* c, const float* d, int g) {
    return g == 0 ? a : (g == 1 ? b : (g == 2 ? c : d));
}

__device__ __forceinline__ float sigm(float x) { return 1.0f / (1.0f + expf(-x)); }

// ============================================================================
// Kernel 1: XS[t][gate*1024+j][b] = sum_i Wx[gate][j][i] * x[b][t][i] + bias
// grid (64, 256): blockIdx.x = hidden-chunk (16 units), blockIdx.y = t
// block tile: M=64 rows (4 gates x 16 units) x N=128 batch, K=512
// ============================================================================
__global__ void __launch_bounds__(256) xproj_kernel(
    const float* __restrict__ x,
    const float* __restrict__ Wg, const float* __restrict__ Wi,
    const float* __restrict__ Wf, const float* __restrict__ Wo,
    const float* __restrict__ bg, const float* __restrict__ bi,
    const float* __restrict__ bf, const float* __restrict__ bo)
{
    __shared__ uint32_t sA[64][36];   // padded: conflict-free frag loads
    __shared__ uint32_t sB[KC][136];

    const int tid = threadIdx.x;
    const int t   = blockIdx.y;
    const int j0  = blockIdx.x * 16;
    if (blockIdx.x == 0 && blockIdx.y == 0 && tid == 0) g_bar = 0;  // reset barrier for lstm kernel

    const int warp = tid >> 5, lane = tid & 31;
    const int wm = warp & 3, wn = warp >> 2;       // 4 M-warps (one per gate) x 2 N-warps
    const int gid = lane >> 2, tig = lane & 3;

    float acc[8][4];
#pragma unroll
    for (int i = 0; i < 8; ++i) { acc[i][0] = acc[i][1] = acc[i][2] = acc[i][3] = 0.f; }

#pragma unroll 1
    for (int kc = 0; kc < INPD / KC; ++kc) {
#pragma unroll
        for (int i = 0; i < 8; ++i) {               // A: 64 rows x 32 k
            int idx = i * 256 + tid, r = idx >> 5, k = idx & 31;
            const float* W = sel4(Wg, Wi, Wf, Wo, r >> 4);
            sA[r][k] = f2tf(W[(size_t)(j0 + (r & 15)) * INPD + kc * KC + k]);
        }
#pragma unroll
        for (int i = 0; i < 16; ++i) {              // B: 32 k x 128 b from x[b][t][k]
            int idx = i * 256 + tid, b = idx >> 5, k = idx & 31;
            sB[k][b] = f2tf(x[(size_t)b * (TSTEPS * INPD) + (size_t)t * INPD + kc * KC + k]);
        }
        __syncthreads();
#pragma unroll
        for (int ks = 0; ks < 4; ++ks) {
            const int k8 = ks * 8;
            uint32_t a[4];
            a[0] = sA[wm * 16 + gid][k8 + tig];
            a[1] = sA[wm * 16 + gid + 8][k8 + tig];
            a[2] = sA[wm * 16 + gid][k8 + tig + 4];
            a[3] = sA[wm * 16 + gid + 8][k8 + tig + 4];
#pragma unroll
            for (int nf = 0; nf < 8; ++nf) {
                const int n = wn * 64 + nf * 8 + gid;
                uint32_t bb[2] = { sB[k8 + tig][n], sB[k8 + tig + 4][n] };
                mma8(acc[nf], a, bb);
            }
        }
        __syncthreads();
    }

    const float* bptr = sel4(bg, bi, bf, bo, wm);
    const float b0v = bptr[j0 + gid];
    const float b1v = bptr[j0 + gid + 8];
    const size_t base = (size_t)t * G4H * BATCH;
    const int g0 = wm * 1024 + j0 + gid;
#pragma unroll
    for (int nf = 0; nf < 8; ++nf) {
        const int n = wn * 64 + nf * 8 + tig * 2;
        float* p0 = &g_XS[base + (size_t)g0 * BATCH + n];
        float* p1 = &g_XS[base + (size_t)(g0 + 8) * BATCH + n];
        p0[0] = acc[nf][0] + b0v; p0[1] = acc[nf][1] + b0v;
        p1[0] = acc[nf][2] + b1v; p1[1] = acc[nf][3] + b1v;
    }
}

// ============================================================================
// Kernel 2: persistent recurrent kernel. 64 blocks, each owns 16 hidden units
// (all 4 gates, full batch). c state in registers for all 256 steps.
// Software grid barrier between steps (all 64 blocks co-resident on 148 SMs).
// ============================================================================
struct SmemU {
    union {
        struct { uint32_t A[64][36]; uint32_t B[KC][136]; } ab;
        float zs[64][136];
    };
};

__global__ void __launch_bounds__(256) lstm_kernel(
    const float* __restrict__ h0, const float* __restrict__ c0,
    const float* __restrict__ Wg, const float* __restrict__ Wi,
    const float* __restrict__ Wf, const float* __restrict__ Wo,
    float* __restrict__ out)
{
    __shared__ SmemU sm;
    const int tid = threadIdx.x;
    const int j0  = blockIdx.x * 16;
    const int warp = tid >> 5, lane = tid & 31;
    const int wm = warp & 3, wn = warp >> 2;
    const int gid = lane >> 2, tig = lane & 3;

    // per-thread slice of c state: 8 (j,b) pairs, held in registers across all steps
    float creg[8];
#pragma unroll
    for (int e = 0; e < 8; ++e) {
        int idx = e * 256 + tid, jj = idx >> 7, b = idx & 127;
        creg[e] = c0[(j0 + jj) * BATCH + b];
    }

#pragma unroll 1
    for (int t = 0; t < TSTEPS; ++t) {
        const float* hin = (t == 0) ? h0 : g_H[(t + 1) & 1];

        float acc[8][4];
#pragma unroll
        for (int i = 0; i < 8; ++i) { acc[i][0] = acc[i][1] = acc[i][2] = acc[i][3] = 0.f; }

#pragma unroll 1
        for (int kc = 0; kc < HID / KC; ++kc) {
#pragma unroll
            for (int i = 0; i < 8; ++i) {           // A: Wh rows (64 x 32)
                int idx = i * 256 + tid, r = idx >> 5, k = idx & 31;
                const float* W = sel4(Wg, Wi, Wf, Wo, r >> 4);
                sm.ab.A[r][k] = f2tf(W[(size_t)(j0 + (r & 15)) * HID + kc * KC + k]);
            }
#pragma unroll
            for (int i = 0; i < 16; ++i) {          // B: h[k][b] (32 x 128)
                int idx = i * 256 + tid, k = idx >> 7, b = idx & 127;
                sm.ab.B[k][b] = f2tf(hin[(kc * KC + k) * BATCH + b]);
            }
            __syncthreads();
#pragma unroll
            for (int ks = 0; ks < 4; ++ks) {
                const int k8 = ks * 8;
                uint32_t a[4];
                a[0] = sm.ab.A[wm * 16 + gid][k8 + tig];
                a[1] = sm.ab.A[wm * 16 + gid + 8][k8 + tig];
                a[2] = sm.ab.A[wm * 16 + gid][k8 + tig + 4];
                a[3] = sm.ab.A[wm * 16 + gid + 8][k8 + tig + 4];
#pragma unroll
                for (int nf = 0; nf < 8; ++nf) {
                    const int n = wn * 64 + nf * 8 + gid;
                    uint32_t bb[2] = { sm.ab.B[k8 + tig][n], sm.ab.B[k8 + tig + 4][n] };
                    mma8(acc[nf], a, bb);
                }
            }
            __syncthreads();
        }

        // stage z tile into smem so each thread can gather all 4 gates of its (j,b)
#pragma unroll
        for (int nf = 0; nf < 8; ++nf) {
            const int n = wn * 64 + nf * 8 + tig * 2;
            sm.zs[wm * 16 + gid][n]         = acc[nf][0];
            sm.zs[wm * 16 + gid][n + 1]     = acc[nf][1];
            sm.zs[wm * 16 + gid + 8][n]     = acc[nf][2];
            sm.zs[wm * 16 + gid + 8][n + 1] = acc[nf][3];
        }
        __syncthreads();

        float* hw = g_H[t & 1];
        const size_t xb = (size_t)t * G4H * BATCH;
#pragma unroll
        for (int e = 0; e < 8; ++e) {
            int idx = e * 256 + tid, jj = idx >> 7, b = idx & 127;
            const size_t row = (size_t)(j0 + jj) * BATCH + b;
            float zg = sm.zs[jj][b]      + g_XS[xb + row];
            float zi = sm.zs[16 + jj][b] + g_XS[xb + (size_t)1024 * BATCH + row];
            float zf = sm.zs[32 + jj][b] + g_XS[xb + (size_t)2048 * BATCH + row];
            float zo = sm.zs[48 + jj][b] + g_XS[xb + (size_t)3072 * BATCH + row];
            float cv = tanhf(zg) * sigm(zi) + creg[e] * sigm(zf);
            creg[e] = cv;
            float hv = tanhf(cv) * sigm(zo);
            hw[row] = hv;
            if (t == TSTEPS - 1) out[row] = hv;
        }
        __syncthreads();

        // grid barrier: release h writes, arrive, spin until all 64 blocks arrived
        if (tid == 0) {
            __threadfence();
            atomicAdd(&g_bar, 1u);
            const unsigned target = (unsigned)(t + 1) * gridDim.x;
            const volatile unsigned* p = &g_bar;
            while (*p < target) { __nanosleep(64); }
            __threadfence();
        }
        __syncthreads();
    }
}

// ============================================================================
extern "C" void kernel_launch(void* const* d_in, const int* in_sizes, int n_in,
                              void* d_out, int out_size)
{
    const float* x   = (const float*)d_in[0];
    const float* c0  = (const float*)d_in[1];
    const float* h0  = (const float*)d_in[2];
    const float* Wgx = (const float*)d_in[3];
    const float* Wix = (const float*)d_in[4];
    const float* Wfx = (const float*)d_in[5];
    const float* Wox = (const float*)d_in[6];
    const float* Wgh = (const float*)d_in[7];
    const float* Wih = (const float*)d_in[8];
    const float* Wfh = (const float*)d_in[9];
    const float* Woh = (const float*)d_in[10];
    const float* bg  = (const float*)d_in[11];
    const float* bi  = (const float*)d_in[12];
    const float* bf  = (const float*)d_in[13];
    const float* bo  = (const float*)d_in[14];
    float* out = (float*)d_out;

    dim3 gproj(64, TSTEPS, 1);
    xproj_kernel<<<gproj, 256>>>(x, Wgx, Wix, Wfx, Wox, bg, bi, bf, bo);
    lstm_kernel<<<64, 256>>>(h0, c0, Wgh, Wih, Wfh, Woh, out);
}

// round 5
// speedup vs baseline: 3.8239x; 3.8239x over previous
#include <cuda_runtime.h>
#include <cstdint>

#define HID    1024
#define INPD   512
#define BATCH  128
#define TSTEPS 256
#define G4H    4096
#define NB     128      // lstm persistent blocks
#define LT     512      // lstm threads

// ---- device-global scratch (no allocations allowed) ----
__device__ float    g_XS[134217728];          // [t][gate*1024+j][b] fp32 (512 MB)
__device__ uint32_t g_XT[512u * 32768u];      // x transposed+tf32: [i][t*128+b] (64 MB)
__device__ uint32_t g_WXp[4096u * 512u];      // Wx concat, tf32, fragment-permuted (8 MB)
__device__ float    g_H[2][HID * BATCH];      // h ping-pong (values pre-rounded to tf32)
__device__ unsigned g_bar;

__device__ __forceinline__ uint32_t f2tf(float f) {
    uint32_t u;
    asm("cvt.rna.tf32.f32 %0, %1;" : "=r"(u) : "f"(f));
    return u;
}
__device__ __forceinline__ void mma8(float* d, uint32_t a0, uint32_t a1, uint32_t a2,
                                     uint32_t a3, uint32_t b0, uint32_t b1) {
    asm volatile(
        "mma.sync.aligned.m16n8k8.row.col.f32.tf32.tf32.f32 "
        "{%0,%1,%2,%3}, {%4,%5,%6,%7}, {%8,%9}, {%0,%1,%2,%3};"
        : "+f"(d[0]), "+f"(d[1]), "+f"(d[2]), "+f"(d[3])
        : "r"(a0), "r"(a1), "r"(a2), "r"(a3), "r"(b0), "r"(b1));
}
__device__ __forceinline__ const float* sel4(const float* a, const float* b,
                                             const float* c, const float* d, int g) {
    return g == 0 ? a : (g == 1 ? b : (g == 2 ? c : d));
}
__device__ __forceinline__ float sigm(float x) { return 1.0f / (1.0f + expf(-x)); }

__device__ __forceinline__ void cp16(uint32_t dst, const void* src) {
    asm volatile("cp.async.cg.shared.global [%0], [%1], 16;" :: "r"(dst), "l"(src));
}
__device__ __forceinline__ void cpcommit() { asm volatile("cp.async.commit_group;"); }
template<int N> __device__ __forceinline__ void cpwait() {
    asm volatile("cp.async.wait_group %0;" :: "n"(N));
}

// ============================================================================
// prep_w: round Wx-concat to tf32 and store FRAGMENT-PERMUTED:
//   g_WXp[(((R>>4)*64 + k8)*32 + lane)*4 + j]  holds the exact m16n8k8 A-frag regs
//   (j=0:(gid,tig) j=1:(gid+8,tig) j=2:(gid,tig+4) j=3:(gid+8,tig+4))
// also resets the grid-barrier counter.
// ============================================================================
__global__ void prep_w_kernel(const float* __restrict__ Wg, const float* __restrict__ Wi,
                              const float* __restrict__ Wf, const float* __restrict__ Wo) {
    if (blockIdx.x == 0 && threadIdx.x == 0) g_bar = 0;
    int base = blockIdx.x * 256 + threadIdx.x;
#pragma unroll
    for (int i = 0; i < 4; ++i) {
        int o  = base + i * 524288;
        int j  = o & 3, ln = (o >> 2) & 31, k8 = (o >> 7) & 63, rb = o >> 13;
        int R  = rb * 16 + (ln >> 2) + (j & 1) * 8;
        int k  = k8 * 8 + (ln & 3) + ((j >> 1) & 1) * 4;
        const float* W = sel4(Wg, Wi, Wf, Wo, R >> 10);
        g_WXp[o] = f2tf(W[(size_t)(R & 1023) * INPD + k]);
    }
}

// ============================================================================
// prep_xt: transpose + tf32-round x:  g_XT[i][t*128+b] = tf32(x[b][t][i])
// ============================================================================
__global__ void prep_xt_kernel(const float* __restrict__ x) {
    __shared__ float tile[32][33];
    int tx = threadIdx.x & 31, ty = threadIdx.x >> 5;
    int it = blockIdx.x, nt = blockIdx.y;
#pragma unroll
    for (int r = 0; r < 4; ++r) {
        int n = nt * 32 + ty + r * 8;
        int t = n >> 7, b = n & 127;
        tile[ty + r * 8][tx] = x[(size_t)b * (TSTEPS * INPD) + t * INPD + it * 32 + tx];
    }
    __syncthreads();
#pragma unroll
    for (int r = 0; r < 4; ++r) {
        int il = ty + r * 8;
        g_XT[(size_t)(it * 32 + il) * 32768 + nt * 32 + tx] = f2tf(tile[tx][il]);
    }
}

// ============================================================================
// xproj: XS[t][R][b] = Wx[R]·x[b][t] + bias[R].  Tile M=128 x N=128(one t) x K=512.
// All operands pre-rounded -> pure cp.async double-buffered pipeline.
// grid (32, 256), 256 threads (8 warps = 2M x 4N, warp tile 64x32).
// ============================================================================
__global__ void __launch_bounds__(256, 2) xproj_kernel(
    const float* __restrict__ bg, const float* __restrict__ bi,
    const float* __restrict__ bf, const float* __restrict__ bo) {
    extern __shared__ uint32_t sm[];
    uint32_t* sA = sm;                  // 2 bufs x 4096 u32  (frag layout)
    uint32_t* sB = sm + 8192;           // 2 bufs x 32 x 136 u32
    const uint32_t smem0 = (uint32_t)__cvta_generic_to_shared(sm);
    const int tid = threadIdx.x;
    const int m_base = blockIdx.x * 128;
    const int t = blockIdx.y;
    const int warp = tid >> 5, lane = tid & 31;
    const int wm = warp & 1, wn = warp >> 1;
    const int gid = lane >> 2, tig = lane & 3;

    float acc[4][4][4];
#pragma unroll
    for (int a = 0; a < 4; ++a)
#pragma unroll
        for (int b = 0; b < 4; ++b) {
            acc[a][b][0] = acc[a][b][1] = acc[a][b][2] = acc[a][b][3] = 0.f;
        }

    auto issue = [&](int kc, int buf) {
#pragma unroll
        for (int c = 0; c < 4; ++c) {                       // A: 16 KB frag-linear
            int u = c * 256 + tid;
            int rbl = u >> 7, q = u & 127;
            const uint32_t* src = g_WXp + (size_t)(((m_base >> 4) + rbl) * 64 + kc * 4) * 128 + q * 4;
            cp16(smem0 + (uint32_t)(buf * 4096 + rbl * 512 + q * 4) * 4, src);
        }
#pragma unroll
        for (int c = 0; c < 4; ++c) {                       // B: 32k x 128b
            int u = c * 256 + tid;
            int k = u >> 5, b4 = u & 31;
            const uint32_t* src = g_XT + (size_t)(kc * 32 + k) * 32768 + t * 128 + b4 * 4;
            cp16(smem0 + (uint32_t)(8192 + buf * 4352 + k * 136 + b4 * 4) * 4, src);
        }
    };
    issue(0, 0); cpcommit();
    issue(1, 1); cpcommit();

#pragma unroll 1
    for (int kc = 0; kc < 16; ++kc) {
        if (kc < 15) cpwait<1>(); else cpwait<0>();
        __syncthreads();
        const uint32_t* A = sA + (kc & 1) * 4096;
        const uint32_t* B = sB + (kc & 1) * 4352;
#pragma unroll
        for (int k8 = 0; k8 < 4; ++k8) {
            uint4 af[4];
#pragma unroll
            for (int mf = 0; mf < 4; ++mf)
                af[mf] = *(const uint4*)(A + (wm * 4 + mf) * 512 + k8 * 128 + lane * 4);
#pragma unroll
            for (int nf = 0; nf < 4; ++nf) {
                int n = wn * 32 + nf * 8 + gid;
                uint32_t b0 = B[(k8 * 8 + tig) * 136 + n];
                uint32_t b1 = B[(k8 * 8 + tig + 4) * 136 + n];
#pragma unroll
                for (int mf = 0; mf < 4; ++mf)
                    mma8(acc[mf][nf], af[mf].x, af[mf].y, af[mf].z, af[mf].w, b0, b1);
            }
        }
        __syncthreads();
        if (kc + 2 < 16) { issue(kc + 2, kc & 1); cpcommit(); }
    }

#pragma unroll
    for (int mf = 0; mf < 4; ++mf) {
        int R0 = m_base + wm * 64 + mf * 16 + gid;
        int R1 = R0 + 8;
        float bv0 = sel4(bg, bi, bf, bo, R0 >> 10)[R0 & 1023];
        float bv1 = sel4(bg, bi, bf, bo, R1 >> 10)[R1 & 1023];
#pragma unroll
        for (int nf = 0; nf < 4; ++nf) {
            int cc = wn * 32 + nf * 8 + tig * 2;
            float2 v0 = { acc[mf][nf][0] + bv0, acc[mf][nf][1] + bv0 };
            float2 v1 = { acc[mf][nf][2] + bv1, acc[mf][nf][3] + bv1 };
            *(float2*)&g_XS[((size_t)t * G4H + R0) * BATCH + cc] = v0;
            *(float2*)&g_XS[((size_t)t * G4H + R1) * BATCH + cc] = v1;
        }
    }
}

// ============================================================================
// lstm: 128 persistent blocks, 512 threads. Block owns 8 hidden units x 4 gates
// (M=32). Wh tf32 frag-permuted in smem (128 KB) for the WHOLE kernel.
// h pre-rounded to tf32 by the producer -> consumer uses raw cp.async.
// smem: sW 131072 B | sB 2x34816 B (zs 32x132 f32 overlays sB buf0).
// ============================================================================
__global__ void __launch_bounds__(512, 1) lstm_kernel(
    const float* __restrict__ h0, const float* __restrict__ c0,
    const float* __restrict__ Wg, const float* __restrict__ Wi,
    const float* __restrict__ Wf, const float* __restrict__ Wo,
    float* __restrict__ out) {
    extern __shared__ uint32_t sm[];
    uint32_t* sW = sm;                  // 32768 u32
    uint32_t* sB = sm + 32768;          // 2 x 8704 u32
    float*    zs = (float*)(sm + 32768);
    const uint32_t smem0 = (uint32_t)__cvta_generic_to_shared(sm);
    const int tid = threadIdx.x;
    const int j0 = blockIdx.x * 8;
    const int warp = tid >> 5, lane = tid & 31;
    const int wm = warp & 1, wn = warp >> 1;     // 2 M-warps x 8 N-warps
    const int gid = lane >> 2, tig = lane & 3;
    const int n0 = wn * 16;

    // prologue: fill frag-permuted Wh (tf32) once
#pragma unroll 1
    for (int i = 0; i < 64; ++i) {
        int o  = i * 512 + tid;
        int j  = o & 3, ln = (o >> 2) & 31, k8 = (o >> 7) & 127, mh = o >> 14;
        int row = mh * 16 + (ln >> 2) + (j & 1) * 8;       // row = gate*8 + u
        int k   = k8 * 8 + (ln & 3) + ((j >> 1) & 1) * 4;
        const float* W = sel4(Wg, Wi, Wf, Wo, row >> 3);
        sW[o] = f2tf(W[(size_t)(j0 + (row & 7)) * HID + k]);
    }
    // h0 rounded into g_H[1]; c state into registers
    float creg[2];
#pragma unroll
    for (int e = 0; e < 2; ++e) {
        int idx = e * 512 + tid, u = idx >> 7, b = idx & 127;
        g_H[1][(j0 + u) * BATCH + b] = __uint_as_float(f2tf(h0[(j0 + u) * BATCH + b]));
        creg[e] = c0[(j0 + u) * BATCH + b];
    }
    __syncthreads();
    if (tid == 0) { __threadfence(); atomicAdd(&g_bar, 1u); }

#pragma unroll 1
    for (int t = 0; t < TSTEPS; ++t) {
        // XS prefetch into registers (independent of grid barrier -> hides DRAM latency)
        float xsv[4][2];
        {
            const size_t xb = (size_t)t * (G4H * BATCH);
#pragma unroll
            for (int e = 0; e < 2; ++e) {
                int idx = e * 512 + tid, u = idx >> 7, b = idx & 127;
#pragma unroll
                for (int g = 0; g < 4; ++g)
                    xsv[g][e] = g_XS[xb + (size_t)((g << 10) + j0 + u) * BATCH + b];
            }
        }
        // wait for h(t-1) from all blocks
        if (tid == 0) {
            const unsigned target = (unsigned)(t + 1) * NB;
            volatile unsigned* p = &g_bar;
            while (*p < target) { __nanosleep(64); }
            __threadfence();
        }
        __syncthreads();

        const float* hin = g_H[(t + 1) & 1];
        auto issueB = [&](int kc, int buf) {
#pragma unroll
            for (int c = 0; c < 4; ++c) {
                int u = c * 512 + tid;
                int kl = u >> 5, b4 = u & 31;
                cp16(smem0 + (uint32_t)(32768 + buf * 8704 + kl * 136 + b4 * 4) * 4,
                     hin + (kc * 64 + kl) * BATCH + b4 * 4);
            }
        };
        float acc0[4] = {0, 0, 0, 0}, acc1[4] = {0, 0, 0, 0};
        issueB(0, 0); cpcommit();
        issueB(1, 1); cpcommit();
#pragma unroll 1
        for (int kc = 0; kc < 16; ++kc) {
            if (kc < 15) cpwait<1>(); else cpwait<0>();
            __syncthreads();
            const uint32_t* B  = sB + (kc & 1) * 8704;
            const uint32_t* Wb = sW + ((wm * 128 + kc * 8) * 32 + lane) * 4;
#pragma unroll
            for (int k8 = 0; k8 < 8; ++k8) {
                uint4 af = *(const uint4*)(Wb + k8 * 128);
                uint32_t b00 = B[(k8 * 8 + tig)     * 136 + n0 + gid];
                uint32_t b01 = B[(k8 * 8 + tig + 4) * 136 + n0 + gid];
                uint32_t b10 = B[(k8 * 8 + tig)     * 136 + n0 + 8 + gid];
                uint32_t b11 = B[(k8 * 8 + tig + 4) * 136 + n0 + 8 + gid];
                mma8(acc0, af.x, af.y, af.z, af.w, b00, b01);
                mma8(acc1, af.x, af.y, af.z, af.w, b10, b11);
            }
            __syncthreads();
            if (kc + 2 < 16) { issueB(kc + 2, kc & 1); cpcommit(); }
        }
        // stage z into smem (overlay on sB buf0; last mma used buf1)
        {
            int r0 = wm * 16 + gid;
            zs[r0 * 132 + n0 + tig * 2]           = acc0[0];
            zs[r0 * 132 + n0 + tig * 2 + 1]       = acc0[1];
            zs[(r0 + 8) * 132 + n0 + tig * 2]     = acc0[2];
            zs[(r0 + 8) * 132 + n0 + tig * 2 + 1] = acc0[3];
            zs[r0 * 132 + n0 + 8 + tig * 2]           = acc1[0];
            zs[r0 * 132 + n0 + 8 + tig * 2 + 1]       = acc1[1];
            zs[(r0 + 8) * 132 + n0 + 8 + tig * 2]     = acc1[2];
            zs[(r0 + 8) * 132 + n0 + 8 + tig * 2 + 1] = acc1[3];
        }
        __syncthreads();
        float* hw = g_H[t & 1];
#pragma unroll
        for (int e = 0; e < 2; ++e) {
            int idx = e * 512 + tid, u = idx >> 7, b = idx & 127;
            float zg = zs[u * 132 + b]          + xsv[0][e];
            float zi = zs[(8 + u) * 132 + b]    + xsv[1][e];
            float zf = zs[(16 + u) * 132 + b]   + xsv[2][e];
            float zo = zs[(24 + u) * 132 + b]   + xsv[3][e];
            float cv = tanhf(zg) * sigm(zi) + creg[e] * sigm(zf);
            creg[e] = cv;
            float hv = tanhf(cv) * sigm(zo);
            hw[(j0 + u) * BATCH + b] = __uint_as_float(f2tf(hv));   // pre-rounded for next GEMM
            if (t == TSTEPS - 1) out[(j0 + u) * BATCH + b] = hv;
        }
        __syncthreads();
        if (tid == 0) { __threadfence(); atomicAdd(&g_bar, 1u); }
    }
}

// ============================================================================
extern "C" void kernel_launch(void* const* d_in, const int* in_sizes, int n_in,
                              void* d_out, int out_size) {
    const float* x   = (const float*)d_in[0];
    const float* c0  = (const float*)d_in[1];
    const float* h0  = (const float*)d_in[2];
    const float* Wgx = (const float*)d_in[3];
    const float* Wix = (const float*)d_in[4];
    const float* Wfx = (const float*)d_in[5];
    const float* Wox = (const float*)d_in[6];
    const float* Wgh = (const float*)d_in[7];
    const float* Wih = (const float*)d_in[8];
    const float* Wfh = (const float*)d_in[9];
    const float* Woh = (const float*)d_in[10];
    const float* bg  = (const float*)d_in[11];
    const float* bi  = (const float*)d_in[12];
    const float* bf  = (const float*)d_in[13];
    const float* bo  = (const float*)d_in[14];
    float* out = (float*)d_out;

    cudaFuncSetAttribute(xproj_kernel, cudaFuncAttributeMaxDynamicSharedMemorySize, 67584);
    cudaFuncSetAttribute(lstm_kernel,  cudaFuncAttributeMaxDynamicSharedMemorySize, 200704);

    prep_w_kernel<<<2048, 256>>>(Wgx, Wix, Wfx, Wox);
    prep_xt_kernel<<<dim3(16, 1024), 256>>>(x);
    xproj_kernel<<<dim3(32, 256), 256, 67584>>>(bg, bi, bf, bo);
    lstm_kernel<<<NB, 512, 200704>>>(h0, c0, Wgh, Wih, Wfh, Woh, out);
}